// round 1
// baseline (speedup 1.0000x reference)
#include <cuda_runtime.h>

#define NSITE 40
#define NCTA  144
#define NTHR  256

// Persistent device scratch (no allocations allowed).
__device__ __align__(16) float g_L[2][131072];   // env L[a][w][b] : a*1024 + w*128 + b
__device__ __align__(16) float g_N[2][16384];    // env N[a][b]    : a*128 + b
__device__ __align__(16) float g_T1[262144];     // [p][(w*2+i)][b]: p*2048 + wi*128 + b
__device__ __align__(16) float g_Tn[32768];      // [p][(b*2+i)]   : p*256 + b*2 + i
__device__ unsigned g_barcnt;

struct PA { float A[128][32]; float B[128][64]; };                       // 48 KB
struct PB { float h[256]; float T1[16][128]; float T2[8][256]; float m[32][128]; }; // 33 KB
struct NBs { float A[32][256]; float B[32][32]; };                      // 36 KB
union __align__(16) Smem { PA pa; PB pb; NBs nb; };

__device__ __forceinline__ void gridbar(unsigned target) {
    __syncthreads();
    if (threadIdx.x == 0) {
        __threadfence();
        atomicAdd(&g_barcnt, 1u);
        volatile unsigned* c = &g_barcnt;
        while (*c < target) { }
        __threadfence();
    }
    __syncthreads();
}

// Shared 32x64 output tile, K=128 GEMM: out[row, col] = sum_k A[k][row] * B[k][col]
// A rows contiguous (stride 1), k-stride = kstrideA. B at Bbase + k*256 + col (64 contiguous).
// Each thread (8 warps x 32 lanes): row = lane, cols = wid*8 .. wid*8+7.
__device__ __forceinline__ void tileGemmK128(Smem* sm,
                                             const float* Abase, int kstrideA,
                                             const float* Bbase,
                                             int tid, float acc[8]) {
    for (int t = tid; t < 4096; t += NTHR) {
        int a = t >> 5;
        sm->pa.A[a][t & 31] = Abase[a * kstrideA + (t & 31)];
    }
    for (int t = tid; t < 8192; t += NTHR) {
        int a = t >> 6;
        sm->pa.B[a][t & 63] = Bbase[a * 256 + (t & 63)];
    }
    __syncthreads();
    int lane = tid & 31, wid = tid >> 5;
#pragma unroll
    for (int j = 0; j < 8; ++j) acc[j] = 0.0f;
#pragma unroll 4
    for (int k = 0; k < 128; ++k) {
        float av = sm->pa.A[k][lane];
        float4 b0 = *(const float4*)&sm->pa.B[k][wid * 8];
        float4 b1 = *(const float4*)&sm->pa.B[k][wid * 8 + 4];
        acc[0] += av * b0.x; acc[1] += av * b0.y;
        acc[2] += av * b0.z; acc[3] += av * b0.w;
        acc[4] += av * b1.x; acc[5] += av * b1.y;
        acc[6] += av * b1.z; acc[7] += av * b1.w;
    }
}

__global__ void mps_init_kernel() {
    int i = blockIdx.x * NTHR + threadIdx.x;   // 576*256 = 147456 threads
    if (i == 0) g_barcnt = 0u;
    if (i < 131072) {
        g_L[0][i] = (i == 0) ? 1.0f : 0.0f;
    } else {
        int j = i - 131072;                    // j < 16384
        g_N[0][j] = (j == 0) ? 1.0f : 0.0f;
    }
}

__global__ void __launch_bounds__(NTHR, 1)
mps_kernel(const float* __restrict__ Mg, const float* __restrict__ Hg, float* __restrict__ out) {
    __shared__ Smem sm;
    const int bid = blockIdx.x;
    const int tid = threadIdx.x;
    const int lane = tid & 31, wid = tid >> 5;
    unsigned nb = 0;
    int cur = 0;

    for (int s = 0; s < NSITE; ++s) {
        const float* m = Mg + s * 32768;   // m[a][i][p] = a*256 + i*128 + p
        const float* h = Hg + s * 256;     // h[w][x][i][j] = w*32 + x*4 + i*2 + j
        const int nxt = cur ^ 1;

        // ---------------- Phase A ----------------
        if (bid < 128) {
            // GEMM1: T1[(w,b),(i,p)] = sum_a L[a,w,b] m[a,i,p]
            int w    = bid >> 4;
            int bch  = (bid >> 2) & 3;
            int ipch = bid & 3;
            float acc[8];
            tileGemmK128(&sm, g_L[cur] + w * 128 + bch * 32, 1024,
                         m + ipch * 64, tid, acc);
            int b = bch * 32 + lane;
#pragma unroll
            for (int j = 0; j < 8; ++j) {
                int col = ipch * 64 + wid * 8 + j;   // col = i*128 + p
                int i = col >> 7, p = col & 127;
                g_T1[p * 2048 + (w * 2 + i) * 128 + b] = acc[j];
            }
        } else {
            // normA: Tn[b,(i,p)] = sum_a N[a,b] m[a,i,p]
            int r    = bid - 128;
            int bch  = r >> 2;
            int ipch = r & 3;
            float acc[8];
            tileGemmK128(&sm, g_N[cur] + bch * 32, 128,
                         m + ipch * 64, tid, acc);
            int b = bch * 32 + lane;
#pragma unroll
            for (int j = 0; j < 8; ++j) {
                int col = ipch * 64 + wid * 8 + j;
                int i = col >> 7, p = col & 127;
                g_Tn[p * 256 + b * 2 + i] = acc[j];
            }
        }
        ++nb; gridbar(nb * NCTA);

        // ---------------- Phase B ----------------
        if (bid < 128) {
            // Fused step2+step3 for one p:
            //   T2[x][(b,j)] = sum_{w,i} T1[p][(w,i)][b] * h[w,x,i,j]
            //   L'[p,x,q]    = sum_{(b,j)} T2[x][(b,j)] * m[(b,j)*... = k*128 + q]
            int p = bid;
            sm.pb.h[tid] = h[tid];
            for (int t = tid; t < 2048; t += NTHR)
                sm.pb.T1[t >> 7][t & 127] = g_T1[p * 2048 + t];
            __syncthreads();
            {
                int b = tid >> 1, j = tid & 1;
                float t1v[16];
#pragma unroll
                for (int wi = 0; wi < 16; ++wi) t1v[wi] = sm.pb.T1[wi][b];
#pragma unroll
                for (int x = 0; x < 8; ++x) {
                    float a = 0.0f;
#pragma unroll
                    for (int wi = 0; wi < 16; ++wi)
                        a += t1v[wi] * sm.pb.h[(wi >> 1) * 32 + x * 4 + (wi & 1) * 2 + j];
                    sm.pb.T2[x][b * 2 + j] = a;
                }
            }
            __syncthreads();
            int x = wid;                      // warp -> x, lane -> q = 4*lane..4*lane+3
            float4 acc = make_float4(0.f, 0.f, 0.f, 0.f);
            for (int kt = 0; kt < 8; ++kt) {
                for (int t = tid; t < 4096; t += NTHR)
                    sm.pb.m[t >> 7][t & 127] = m[(kt * 32 + (t >> 7)) * 128 + (t & 127)];
                __syncthreads();
#pragma unroll 4
                for (int k = 0; k < 32; ++k) {
                    float a = sm.pb.T2[x][kt * 32 + k];
                    float4 mv = *(const float4*)&sm.pb.m[k][lane * 4];
                    acc.x += a * mv.x; acc.y += a * mv.y;
                    acc.z += a * mv.z; acc.w += a * mv.w;
                }
                __syncthreads();
            }
            *(float4*)&g_L[nxt][p * 1024 + x * 128 + lane * 4] = acc;
        } else {
            // normB: N'[p,q] = sum_{k=(b,i)} Tn[p][k] * m[k*128 + q]
            int r = bid - 128;
            int p0 = (r >> 2) * 32, q0 = (r & 3) * 32;
            for (int t = tid; t < 8192; t += NTHR)
                sm.nb.A[t >> 8][t & 255] = g_Tn[(p0 + (t >> 8)) * 256 + (t & 255)];
            __syncthreads();
            float acc[4] = {0.f, 0.f, 0.f, 0.f};
            for (int kt = 0; kt < 8; ++kt) {
                for (int t = tid; t < 1024; t += NTHR)
                    sm.nb.B[t >> 5][t & 31] = m[(kt * 32 + (t >> 5)) * 128 + q0 + (t & 31)];
                __syncthreads();
#pragma unroll 4
                for (int k = 0; k < 32; ++k) {
                    float bv = sm.nb.B[k][lane];
#pragma unroll
                    for (int u = 0; u < 4; ++u)
                        acc[u] += sm.nb.A[wid * 4 + u][kt * 32 + k] * bv;
                }
                __syncthreads();
            }
#pragma unroll
            for (int u = 0; u < 4; ++u)
                g_N[nxt][(p0 + wid * 4 + u) * 128 + q0 + lane] = acc[u];
        }
        ++nb; gridbar(nb * NCTA);

        cur = nxt;
    }

    if (bid == 0 && tid == 0) {
        float e = g_L[cur][7 * 128];     // L[0, W-1, 0]
        float n = g_N[cur][0];           // N[0, 0]
        out[0] = e;
        out[1] = n;
        out[2] = e / n;
        out[3] = fmaxf(n - 10000.0f, 0.0f);
    }
}

extern "C" void kernel_launch(void* const* d_in, const int* in_sizes, int n_in,
                              void* d_out, int out_size) {
    const float* M = (const float*)d_in[0];
    const float* H = (const float*)d_in[1];
    float* out = (float*)d_out;
    mps_init_kernel<<<576, NTHR>>>();
    mps_kernel<<<NCTA, NTHR>>>(M, H, out);
}

// round 2
// speedup vs baseline: 1.8200x; 1.8200x over previous
#include <cuda_runtime.h>

#define NSITE 40
#define NCTA  144
#define NTHR  256

typedef unsigned long long ull;

// Persistent device scratch (no allocations allowed).
__device__ __align__(16) float g_L[2][131072];   // env L[a][w][b] : a*1024 + w*128 + b
__device__ __align__(16) float g_N[2][16384];    // env N[a][b]    : a*128 + b
__device__ __align__(16) float g_T1[262144];     // [p][(w*2+i)][b]: p*2048 + wi*128 + b
__device__ __align__(16) float g_Tn[32768];      // [p][(b*2+i)]   : p*256 + b*2 + i
__device__ unsigned g_barcnt;

// Dynamic smem layout (bytes):
//  compute CTA (bid < 128):
//    m    [256][128] f  @ 0        (131072)   full per-site ket tensor, [k=(b,j)][q]
//    A    [128][32]  f  @ 131072   (16384)
//    B    [128][64]  f  @ 147456   (32768)
//    h    [256]      f  @ 180224   (1024)
//    T1s  [16][128]  f  @ 181248   (8192)
//    T2s  [8][256]   f  @ 189440   (8192)
//  norm CTA (bid >= 128), aliased over same buffer:
//    mn   [256][32]  f  @ 0        (32768)
//    Tns  [32][264]  f  @ 32768    (33792)   (stride 264 kills bank conflicts)
//    A,B  same offsets as compute
#define SMEM_BYTES 197632

#define OFF_M    0
#define OFF_A    131072
#define OFF_B    147456
#define OFF_H    180224
#define OFF_T1S  181248
#define OFF_T2S  189440
#define OFF_MN   0
#define OFF_TNS  32768

__device__ __forceinline__ void cp16(void* s, const void* g) {
    unsigned sa = (unsigned)__cvta_generic_to_shared(s);
    asm volatile("cp.async.cg.shared.global [%0], [%1], 16;" :: "r"(sa), "l"(g));
}
__device__ __forceinline__ void cp_commit() { asm volatile("cp.async.commit_group;"); }
template <int N> __device__ __forceinline__ void cp_wait() {
    asm volatile("cp.async.wait_group %0;" :: "n"(N));
}

#define PACK2(d, s) asm("mov.b64 %0, {%1, %1};" : "=l"(d) : "r"(__float_as_uint(s)))
#define FFMA2(acc, a, b) asm("fma.rn.f32x2 %0, %1, %2, %0;" : "+l"(acc) : "l"(a), "l"(b))

__device__ __forceinline__ float2 unpk(ull v) {
    unsigned lo, hi;
    asm("mov.b64 {%0, %1}, %2;" : "=r"(lo), "=r"(hi) : "l"(v));
    float2 f; f.x = __uint_as_float(lo); f.y = __uint_as_float(hi);
    return f;
}

__device__ __forceinline__ void gridbar(unsigned target) {
    __syncthreads();
    if (threadIdx.x == 0) {
        __threadfence();
        atomicAdd(&g_barcnt, 1u);
        volatile unsigned* c = &g_barcnt;
        while (*c < target) { }
        __threadfence();
    }
    __syncthreads();
}

__global__ void mps_init_kernel() {
    int i = blockIdx.x * NTHR + threadIdx.x;   // 576*256 = 147456 threads
    if (i == 0) g_barcnt = 0u;
    if (i < 131072) {
        g_L[0][i] = (i == 0) ? 1.0f : 0.0f;
    } else {
        int j = i - 131072;                    // j < 16384
        g_N[0][j] = (j == 0) ? 1.0f : 0.0f;
    }
}

// Phase A main loop: 32-row x 64-col tile, K=128, f32x2 packed.
// A in smem [128][32] (row=k), B in smem [128][64] (row=k).
__device__ __forceinline__ void tileA_compute(const float* A, const float* B,
                                              int lane, int wid, ull acc[4]) {
    acc[0] = acc[1] = acc[2] = acc[3] = 0ull;
#pragma unroll 4
    for (int k = 0; k < 128; ++k) {
        float av = A[k * 32 + lane];
        ull av2; PACK2(av2, av);
        ulonglong2 b0 = *(const ulonglong2*)(B + k * 64 + wid * 8);
        ulonglong2 b1 = *(const ulonglong2*)(B + k * 64 + wid * 8 + 4);
        FFMA2(acc[0], av2, b0.x);
        FFMA2(acc[1], av2, b0.y);
        FFMA2(acc[2], av2, b1.x);
        FFMA2(acc[3], av2, b1.y);
    }
}

__global__ void __launch_bounds__(NTHR, 1)
mps_kernel(const float* __restrict__ Mg, const float* __restrict__ Hg, float* __restrict__ out) {
    extern __shared__ __align__(16) char smem[];
    const int bid = blockIdx.x;
    const int tid = threadIdx.x;
    const int lane = tid & 31, wid = tid >> 5;
    unsigned nb = 0;
    int cur = 0;

    float* smA  = (float*)(smem + OFF_A);
    float* smB  = (float*)(smem + OFF_B);
    float* smM  = (float*)(smem + OFF_M);
    float* smH  = (float*)(smem + OFF_H);
    float* smT1 = (float*)(smem + OFF_T1S);
    float* smT2 = (float*)(smem + OFF_T2S);
    float* smMn = (float*)(smem + OFF_MN);
    float* smTn = (float*)(smem + OFF_TNS);

    const bool isE = (bid < 128);
    // Tile coordinates
    const int w_   = isE ? (bid >> 4) : 0;
    const int bch  = isE ? ((bid >> 2) & 3) : ((bid - 128) >> 2);
    const int ipch = isE ? (bid & 3) : ((bid - 128) & 3);
    const int p0g  = isE ? 0 : (((bid - 128) >> 2) * 32);   // norm-B p tile
    const int q0g  = isE ? 0 : (((bid - 128) & 3) * 32);    // norm-B q tile

    for (int s = 0; s < NSITE; ++s) {
        const float* m = Mg + s * 32768;   // m[a][i][p] = a*256+i*128+p; also [(b,j)][q] = k*128+q
        const float* h = Hg + s * 256;
        const int nxt = cur ^ 1;

        // ============ prefetch (group 0: A,B,h | group 1: m) ============
        {
            const float* Abase = isE ? (g_L[cur] + w_ * 128 + bch * 32)
                                     : (g_N[cur] + bch * 32);
            const int kstr = isE ? 1024 : 128;
            const float* Bbase = m + ipch * 64;
            for (int t = tid; t < 1024; t += NTHR)
                cp16(smA + (t >> 3) * 32 + (t & 7) * 4, Abase + (t >> 3) * kstr + (t & 7) * 4);
            for (int t = tid; t < 2048; t += NTHR)
                cp16(smB + (t >> 4) * 64 + (t & 15) * 4, Bbase + (t >> 4) * 256 + (t & 15) * 4);
            if (isE) {
                for (int t = tid; t < 64; t += NTHR)
                    cp16(smH + t * 4, h + t * 4);
            }
            cp_commit();
            if (isE) {
                // full m [256][128]
                for (int t = tid; t < 8192; t += NTHR)
                    cp16(smM + t * 4, m + t * 4);
            } else {
                // m slice [256][q0g..q0g+32)
                for (int t = tid; t < 2048; t += NTHR)
                    cp16(smMn + (t >> 3) * 32 + (t & 7) * 4, m + (t >> 3) * 128 + q0g + (t & 7) * 4);
            }
            cp_commit();
        }
        cp_wait<1>();        // group 0 (A,B,h) complete; m may still be in flight
        __syncthreads();

        // ============ Phase A ============
        {
            ull acc[4];
            tileA_compute(smA, smB, lane, wid, acc);
            if (isE) {
                int b = bch * 32 + lane;
#pragma unroll
                for (int u = 0; u < 4; ++u) {
                    float2 f = unpk(acc[u]);
                    int col = ipch * 64 + wid * 8 + 2 * u;     // col = i*128 + p
                    int i = col >> 7, p = col & 127;
                    g_T1[p * 2048 + (w_ * 2 + i) * 128 + b] = f.x;
                    g_T1[(p + 1) * 2048 + (w_ * 2 + i) * 128 + b] = f.y;
                }
            } else {
                int b = bch * 32 + lane;
#pragma unroll
                for (int u = 0; u < 4; ++u) {
                    float2 f = unpk(acc[u]);
                    int col = ipch * 64 + wid * 8 + 2 * u;
                    int i = col >> 7, p = col & 127;
                    g_Tn[p * 256 + b * 2 + i] = f.x;
                    g_Tn[(p + 1) * 256 + b * 2 + i] = f.y;
                }
            }
        }
        ++nb; gridbar(nb * NCTA);

        // ============ Phase B ============
        if (isE) {
            const int p = bid;
            // stage T1[p] (8 KB)
            for (int t = tid; t < 512; t += NTHR)
                cp16(smT1 + t * 4, g_T1 + p * 2048 + t * 4);
            cp_commit();
            cp_wait<0>();    // T1 + full m resident
            __syncthreads();
            // T2[x][(b,j)] = sum_{w,i} T1[(w,i)][b] * h[w,x,i,j]
            {
                int b = tid >> 1, j = tid & 1;
                float t1v[16];
#pragma unroll
                for (int wi = 0; wi < 16; ++wi) t1v[wi] = smT1[wi * 128 + b];
#pragma unroll
                for (int x = 0; x < 8; ++x) {
                    float a = 0.0f;
#pragma unroll
                    for (int wi = 0; wi < 16; ++wi)
                        a += t1v[wi] * smH[(wi >> 1) * 32 + x * 4 + (wi & 1) * 2 + j];
                    smT2[x * 256 + b * 2 + j] = a;
                }
            }
            __syncthreads();
            // L'[p,x,q] = sum_k T2[x][k] * m[k][q], k=0..255, q = lane*4..+3
            const int x = wid;
            ull a0 = 0ull, a1 = 0ull;
#pragma unroll 4
            for (int k = 0; k < 256; ++k) {
                float t2 = smT2[x * 256 + k];
                ull t2p; PACK2(t2p, t2);
                ulonglong2 mv = *(const ulonglong2*)(smM + k * 128 + lane * 4);
                FFMA2(a0, t2p, mv.x);
                FFMA2(a1, t2p, mv.y);
            }
            float2 f0 = unpk(a0), f1 = unpk(a1);
            float4 o; o.x = f0.x; o.y = f0.y; o.z = f1.x; o.w = f1.y;
            *(float4*)&g_L[nxt][p * 1024 + x * 128 + lane * 4] = o;
        } else {
            // stage Tn[p0g..p0g+32)[256] with padded stride 264
            for (int t = tid; t < 2048; t += NTHR)
                cp16(smTn + (t >> 6) * 264 + (t & 63) * 4,
                     g_Tn + (p0g + (t >> 6)) * 256 + (t & 63) * 4);
            cp_commit();
            cp_wait<0>();
            __syncthreads();
            // N'[p,q] = sum_k Tn[p][k] * m[k][q] ; thread = 2p x 2q tile
            const int qp = tid & 15;        // q pair index
            const int pr = tid >> 4;        // row-pair index (16 values)
            const int r0 = 2 * pr, r1 = 2 * pr + 1;
            ull a0 = 0ull, a1 = 0ull;
#pragma unroll 4
            for (int k = 0; k < 256; ++k) {
                float A0 = smTn[r0 * 264 + k];
                float A1 = smTn[r1 * 264 + k];
                ull pk0, pk1; PACK2(pk0, A0); PACK2(pk1, A1);
                ull mv = *(const ull*)(smMn + k * 32 + qp * 2);
                FFMA2(a0, pk0, mv);
                FFMA2(a1, pk1, mv);
            }
            float2 f0 = unpk(a0), f1 = unpk(a1);
            *(float2*)&g_N[nxt][(p0g + r0) * 128 + q0g + 2 * qp] = f0;
            *(float2*)&g_N[nxt][(p0g + r1) * 128 + q0g + 2 * qp] = f1;
        }
        ++nb; gridbar(nb * NCTA);

        cur = nxt;
    }

    if (bid == 0 && tid == 0) {
        volatile float* Lv = g_L[cur];
        volatile float* Nv = g_N[cur];
        float e = Lv[7 * 128];    // L[0, W-1, 0]
        float n = Nv[0];          // N[0, 0]
        out[0] = e;
        out[1] = n;
        out[2] = e / n;
        out[3] = fmaxf(n - 10000.0f, 0.0f);
    }
}

extern "C" void kernel_launch(void* const* d_in, const int* in_sizes, int n_in,
                              void* d_out, int out_size) {
    const float* M = (const float*)d_in[0];
    const float* H = (const float*)d_in[1];
    float* out = (float*)d_out;
    cudaFuncSetAttribute(mps_kernel, cudaFuncAttributeMaxDynamicSharedMemorySize, SMEM_BYTES);
    mps_init_kernel<<<576, NTHR>>>();
    mps_kernel<<<NCTA, NTHR, SMEM_BYTES>>>(M, H, out);
}

// round 3
// speedup vs baseline: 2.2004x; 1.2090x over previous
#include <cuda_runtime.h>

#define NSITE 40
#define NCTA  144
#define NTHR  256

typedef unsigned long long ull;

// Persistent device scratch (no allocations allowed).
__device__ __align__(16) float g_L[2][131072];   // env L[a][w][b] : a*1024 + w*128 + b
__device__ __align__(16) float g_N[2][16384];    // env N[a][b]    : a*128 + b
__device__ __align__(16) float g_T1[262144];     // [p][(w*2+i)][b]: p*2048 + wi*128 + b
__device__ __align__(16) float g_Tn[32768];      // TRANSPOSED: [k=(2b+i)][p] : k*128 + p
__device__ unsigned g_barcnt;

// Dynamic smem layout (bytes):
//  energy CTA (bid < 128):
//    m    [256][128] f   @ 0        (131072)
//    A    [128][32]  f   @ 131072   (16384)   } A/B region reused as
//    B    [128][64]  f   @ 147456   (32768)   } partial[8][8][128] f (16KB) in Phase B
//    h    [256]      f   @ 180224   (1024)
//    T1s  [16][128]  f   @ 181248   (8192)
//    T2p  [256][8]  ull  @ 189440   (16384)
//  norm CTA (bid >= 128), aliased:
//    mn   [256][32]  f   @ 0        (32768)
//    Tns  [256][32]  f   @ 32768    (32768)
//    A,B same; partial[8][16][32] ull (32KB) aliases A/B region
#define SMEM_BYTES 205824

#define OFF_M    0
#define OFF_A    131072
#define OFF_B    147456
#define OFF_PART 131072
#define OFF_H    180224
#define OFF_T1S  181248
#define OFF_T2P  189440
#define OFF_MN   0
#define OFF_TNS  32768

__device__ __forceinline__ void cp16(void* s, const void* g) {
    unsigned sa = (unsigned)__cvta_generic_to_shared(s);
    asm volatile("cp.async.cg.shared.global [%0], [%1], 16;" :: "r"(sa), "l"(g));
}
__device__ __forceinline__ void cp_commit() { asm volatile("cp.async.commit_group;"); }
template <int N> __device__ __forceinline__ void cp_wait() {
    asm volatile("cp.async.wait_group %0;" :: "n"(N));
}

#define PACK2(d, s) asm("mov.b64 %0, {%1, %1};" : "=l"(d) : "r"(__float_as_uint(s)))
#define FFMA2(acc, a, b) asm("fma.rn.f32x2 %0, %1, %2, %0;" : "+l"(acc) : "l"(a), "l"(b))
#define FADD2(acc, a)    asm("add.rn.f32x2 %0, %0, %1;"     : "+l"(acc) : "l"(a))

__device__ __forceinline__ float2 unpk(ull v) {
    unsigned lo, hi;
    asm("mov.b64 {%0, %1}, %2;" : "=r"(lo), "=r"(hi) : "l"(v));
    float2 f; f.x = __uint_as_float(lo); f.y = __uint_as_float(hi);
    return f;
}

__device__ __forceinline__ void gridbar(unsigned target) {
    __syncthreads();
    if (threadIdx.x == 0) {
        __threadfence();
        atomicAdd(&g_barcnt, 1u);
        volatile unsigned* c = &g_barcnt;
        while (*c < target) { }
        __threadfence();
    }
    __syncthreads();
}

__global__ void mps_init_kernel() {
    int i = blockIdx.x * NTHR + threadIdx.x;   // 576*256 = 147456 threads
    if (i == 0) g_barcnt = 0u;
    if (i < 131072) {
        g_L[0][i] = (i == 0) ? 1.0f : 0.0f;
    } else {
        int j = i - 131072;
        g_N[0][j] = (j == 0) ? 1.0f : 0.0f;
    }
}

// Phase A: 32-row x 64-col tile, K=128, f32x2 packed.
__device__ __forceinline__ void tileA_compute(const float* A, const float* B,
                                              int lane, int wid, ull acc[4]) {
    acc[0] = acc[1] = acc[2] = acc[3] = 0ull;
#pragma unroll 4
    for (int k = 0; k < 128; ++k) {
        float av = A[k * 32 + lane];
        ull av2; PACK2(av2, av);
        ulonglong2 b0 = *(const ulonglong2*)(B + k * 64 + wid * 8);
        ulonglong2 b1 = *(const ulonglong2*)(B + k * 64 + wid * 8 + 4);
        FFMA2(acc[0], av2, b0.x);
        FFMA2(acc[1], av2, b0.y);
        FFMA2(acc[2], av2, b1.x);
        FFMA2(acc[3], av2, b1.y);
    }
}

__global__ void __launch_bounds__(NTHR, 1)
mps_kernel(const float* __restrict__ Mg, const float* __restrict__ Hg, float* __restrict__ out) {
    extern __shared__ __align__(16) char smem[];
    const int bid = blockIdx.x;
    const int tid = threadIdx.x;
    const int lane = tid & 31, wid = tid >> 5;
    unsigned nb = 0;
    int cur = 0;

    float* smA  = (float*)(smem + OFF_A);
    float* smB  = (float*)(smem + OFF_B);
    float* smM  = (float*)(smem + OFF_M);
    float* smH  = (float*)(smem + OFF_H);
    float* smT1 = (float*)(smem + OFF_T1S);
    ull*   smT2p = (ull*)(smem + OFF_T2P);
    float* smMn = (float*)(smem + OFF_MN);
    float* smTn = (float*)(smem + OFF_TNS);
    float* smPartF = (float*)(smem + OFF_PART);
    ull*   smPartU = (ull*)(smem + OFF_PART);

    const bool isE = (bid < 128);
    const int w_   = isE ? (bid >> 4) : 0;
    const int bch  = isE ? ((bid >> 2) & 3) : ((bid - 128) >> 2);
    const int ipch = isE ? (bid & 3) : ((bid - 128) & 3);
    const int p0g  = isE ? 0 : (((bid - 128) >> 2) * 32);
    const int q0g  = isE ? 0 : (((bid - 128) & 3) * 32);

    for (int s = 0; s < NSITE; ++s) {
        const float* m = Mg + s * 32768;   // m[a][i][p] = a*256+i*128+p; as [k=(2b+j)][q] = k*128+q
        const float* h = Hg + s * 256;
        const int nxt = cur ^ 1;

        // ============ prefetch (group 0: A,B,h | group 1: m) ============
        {
            const float* Abase = isE ? (g_L[cur] + w_ * 128 + bch * 32)
                                     : (g_N[cur] + bch * 32);
            const int kstr = isE ? 1024 : 128;
            const float* Bbase = m + ipch * 64;
            for (int t = tid; t < 1024; t += NTHR)
                cp16(smA + (t >> 3) * 32 + (t & 7) * 4, Abase + (t >> 3) * kstr + (t & 7) * 4);
            for (int t = tid; t < 2048; t += NTHR)
                cp16(smB + (t >> 4) * 64 + (t & 15) * 4, Bbase + (t >> 4) * 256 + (t & 15) * 4);
            if (isE) {
                for (int t = tid; t < 64; t += NTHR)
                    cp16(smH + t * 4, h + t * 4);
            }
            cp_commit();
            if (isE) {
                for (int t = tid; t < 8192; t += NTHR)
                    cp16(smM + t * 4, m + t * 4);
            } else {
                for (int t = tid; t < 2048; t += NTHR)
                    cp16(smMn + (t >> 3) * 32 + (t & 7) * 4, m + (t >> 3) * 128 + q0g + (t & 7) * 4);
            }
            cp_commit();
        }
        cp_wait<1>();
        __syncthreads();

        // ============ Phase A ============
        {
            ull acc[4];
            tileA_compute(smA, smB, lane, wid, acc);
            int b = bch * 32 + lane;
            if (isE) {
#pragma unroll
                for (int u = 0; u < 4; ++u) {
                    float2 f = unpk(acc[u]);
                    int col = ipch * 64 + wid * 8 + 2 * u;     // col = i*128 + p
                    int i = col >> 7, p = col & 127;
                    g_T1[p * 2048 + (w_ * 2 + i) * 128 + b] = f.x;
                    g_T1[(p + 1) * 2048 + (w_ * 2 + i) * 128 + b] = f.y;
                }
            } else {
#pragma unroll
                for (int u = 0; u < 4; ++u) {
                    float2 f = unpk(acc[u]);
                    int col = ipch * 64 + wid * 8 + 2 * u;
                    int i = col >> 7, p = col & 127;
                    *(float2*)&g_Tn[(b * 2 + i) * 128 + p] = f;   // transposed, p even
                }
            }
        }
        ++nb; gridbar(nb * NCTA);

        // ============ Phase B ============
        if (isE) {
            const int p = bid;
            for (int t = tid; t < 512; t += NTHR)
                cp16(smT1 + t * 4, g_T1 + p * 2048 + t * 4);
            cp_commit();
            cp_wait<0>();
            __syncthreads();
            // T2p[k][x] = packed pair (v,v), v = sum_{w,i} T1[(w,i)][b] h[w,x,i,j], k=2b+j=tid
            {
                const int b = tid >> 1, j = tid & 1;
                float t1v[16];
#pragma unroll
                for (int wi = 0; wi < 16; ++wi) t1v[wi] = smT1[wi * 128 + b];
#pragma unroll
                for (int x = 0; x < 8; ++x) {
                    float a = 0.0f;
#pragma unroll
                    for (int wi = 0; wi < 16; ++wi)
                        a += t1v[wi] * smH[(wi >> 1) * 32 + x * 4 + (wi & 1) * 2 + j];
                    ull pk; PACK2(pk, a);
                    smT2p[tid * 8 + x] = pk;
                }
            }
            __syncthreads();
            // main: warp w handles k in [w*32, w*32+32); thread: all 8 x, q = lane*4..+3
            ull acc[8][2];
#pragma unroll
            for (int x = 0; x < 8; ++x) { acc[x][0] = 0ull; acc[x][1] = 0ull; }
#pragma unroll 2
            for (int kk = 0; kk < 32; ++kk) {
                const int k = wid * 32 + kk;
                ulonglong2 mv = *(const ulonglong2*)(smM + k * 128 + lane * 4);
                ulonglong2 ta = *(const ulonglong2*)(smT2p + k * 8);
                ulonglong2 tb = *(const ulonglong2*)(smT2p + k * 8 + 2);
                ulonglong2 tc = *(const ulonglong2*)(smT2p + k * 8 + 4);
                ulonglong2 td = *(const ulonglong2*)(smT2p + k * 8 + 6);
                FFMA2(acc[0][0], ta.x, mv.x); FFMA2(acc[0][1], ta.x, mv.y);
                FFMA2(acc[1][0], ta.y, mv.x); FFMA2(acc[1][1], ta.y, mv.y);
                FFMA2(acc[2][0], tb.x, mv.x); FFMA2(acc[2][1], tb.x, mv.y);
                FFMA2(acc[3][0], tb.y, mv.x); FFMA2(acc[3][1], tb.y, mv.y);
                FFMA2(acc[4][0], tc.x, mv.x); FFMA2(acc[4][1], tc.x, mv.y);
                FFMA2(acc[5][0], tc.y, mv.x); FFMA2(acc[5][1], tc.y, mv.y);
                FFMA2(acc[6][0], td.x, mv.x); FFMA2(acc[6][1], td.x, mv.y);
                FFMA2(acc[7][0], td.y, mv.x); FFMA2(acc[7][1], td.y, mv.y);
            }
            // partial[w][x][q] floats
#pragma unroll
            for (int x = 0; x < 8; ++x) {
                ulonglong2 v; v.x = acc[x][0]; v.y = acc[x][1];
                *(ulonglong2*)(smPartF + wid * 1024 + x * 128 + lane * 4) = v;
            }
            __syncthreads();
            {
                const int x = wid;
                ull r0 = 0ull, r1 = 0ull;
#pragma unroll
                for (int w2 = 0; w2 < 8; ++w2) {
                    ulonglong2 v = *(const ulonglong2*)(smPartF + w2 * 1024 + x * 128 + lane * 4);
                    FADD2(r0, v.x); FADD2(r1, v.y);
                }
                ulonglong2 o; o.x = r0; o.y = r1;
                *(ulonglong2*)&g_L[nxt][p * 1024 + x * 128 + lane * 4] = o;
            }
        } else {
            // stage Tn rows [256][p0g..p0g+32)
            for (int t = tid; t < 2048; t += NTHR)
                cp16(smTn + (t >> 3) * 32 + (t & 7) * 4,
                     g_Tn + (t >> 3) * 128 + p0g + (t & 7) * 4);
            cp_commit();
            cp_wait<0>();
            __syncthreads();
            // main: warp w -> k in [w*32,+32); thread: q = lane, all 32 p as 16 pairs
            ull acc[16];
#pragma unroll
            for (int u = 0; u < 16; ++u) acc[u] = 0ull;
#pragma unroll 2
            for (int kk = 0; kk < 32; ++kk) {
                const int k = wid * 32 + kk;
                float mq = smMn[k * 32 + lane];
                ull mq2; PACK2(mq2, mq);
#pragma unroll
                for (int c = 0; c < 8; ++c) {
                    ulonglong2 u = *(const ulonglong2*)(smTn + k * 32 + c * 4);
                    FFMA2(acc[2 * c], u.x, mq2);
                    FFMA2(acc[2 * c + 1], u.y, mq2);
                }
            }
            // partial[w][pp][q] ull pairs
#pragma unroll
            for (int pp = 0; pp < 16; ++pp)
                smPartU[wid * 512 + pp * 32 + lane] = acc[pp];
            __syncthreads();
            {
#pragma unroll
                for (int half = 0; half < 2; ++half) {
                    const int pp = wid + half * 8;
                    ull r = 0ull;
#pragma unroll
                    for (int w2 = 0; w2 < 8; ++w2)
                        FADD2(r, smPartU[w2 * 512 + pp * 32 + lane]);
                    float2 f = unpk(r);
                    g_N[nxt][(p0g + 2 * pp) * 128 + q0g + lane] = f.x;
                    g_N[nxt][(p0g + 2 * pp + 1) * 128 + q0g + lane] = f.y;
                }
            }
        }
        ++nb; gridbar(nb * NCTA);

        cur = nxt;
    }

    if (bid == 0 && tid == 0) {
        volatile float* Lv = g_L[cur];
        volatile float* Nv = g_N[cur];
        float e = Lv[7 * 128];    // L[0, W-1, 0]
        float n = Nv[0];          // N[0, 0]
        out[0] = e;
        out[1] = n;
        out[2] = e / n;
        out[3] = fmaxf(n - 10000.0f, 0.0f);
    }
}

extern "C" void kernel_launch(void* const* d_in, const int* in_sizes, int n_in,
                              void* d_out, int out_size) {
    const float* M = (const float*)d_in[0];
    const float* H = (const float*)d_in[1];
    float* out = (float*)d_out;
    cudaFuncSetAttribute(mps_kernel, cudaFuncAttributeMaxDynamicSharedMemorySize, SMEM_BYTES);
    mps_init_kernel<<<576, NTHR>>>();
    mps_kernel<<<NCTA, NTHR, SMEM_BYTES>>>(M, H, out);
}

// round 4
// speedup vs baseline: 2.2031x; 1.0012x over previous
#include <cuda_runtime.h>

#define NSITE 40
#define NCTA  144
#define NTHR  256

typedef unsigned long long ull;

// Persistent device scratch (no allocations allowed).
__device__ __align__(16) float g_L[2][131072];   // env L[a][w][b] : a*1024 + w*128 + b
__device__ __align__(16) float g_N[2][16384];    // env N[a][b]    : a*128 + b
__device__ __align__(16) float g_T1[262144];     // [p][(w*2+i)][b]: p*2048 + wi*128 + b
__device__ __align__(16) float g_Tn[32768];      // TRANSPOSED: [k=(2b+i)][p] : k*128 + p
__device__ unsigned g_barcnt;

// Dynamic smem layout (bytes):
//  energy CTA (bid < 128):
//    m    [256][128] f   @ 0        (131072)
//    A    [128][32]  f   @ 131072   (16384)   } A/B region reused as
//    B    [128][64]  f   @ 147456   (32768)   } partial[8][8][128] f (16KB) in Phase B
//    h    [256]      f   @ 180224   (1024)
//    T1s  [16][128]  f   @ 181248   (8192)
//    T2p  [256][8]  ull  @ 189440   (16384)
//  norm CTA (bid >= 128), aliased:
//    mn   [256][32]  f   @ 0        (32768)
//    Tns  [256][32]  f   @ 32768    (32768)
//    A,B same; partial[8][16][32] ull (32KB) aliases A/B region
#define SMEM_BYTES 205824

#define OFF_M    0
#define OFF_A    131072
#define OFF_B    147456
#define OFF_PART 131072
#define OFF_H    180224
#define OFF_T1S  181248
#define OFF_T2P  189440
#define OFF_MN   0
#define OFF_TNS  32768

__device__ __forceinline__ void cp16(void* s, const void* g) {
    unsigned sa = (unsigned)__cvta_generic_to_shared(s);
    asm volatile("cp.async.cg.shared.global [%0], [%1], 16;" :: "r"(sa), "l"(g));
}
__device__ __forceinline__ void cp_commit() { asm volatile("cp.async.commit_group;"); }
template <int N> __device__ __forceinline__ void cp_wait() {
    asm volatile("cp.async.wait_group %0;" :: "n"(N));
}

#define PACK2(d, s) asm("mov.b64 %0, {%1, %1};" : "=l"(d) : "r"(__float_as_uint(s)))
#define FFMA2(acc, a, b) asm("fma.rn.f32x2 %0, %1, %2, %0;" : "+l"(acc) : "l"(a), "l"(b))
#define FADD2(acc, a)    asm("add.rn.f32x2 %0, %0, %1;"     : "+l"(acc) : "l"(a))

__device__ __forceinline__ float2 unpk(ull v) {
    unsigned lo, hi;
    asm("mov.b64 {%0, %1}, %2;" : "=r"(lo), "=r"(hi) : "l"(v));
    float2 f; f.x = __uint_as_float(lo); f.y = __uint_as_float(hi);
    return f;
}

__device__ __forceinline__ void gridbar(unsigned target) {
    __syncthreads();
    if (threadIdx.x == 0) {
        __threadfence();
        atomicAdd(&g_barcnt, 1u);
        volatile unsigned* c = &g_barcnt;
        while (*c < target) { }
        __threadfence();
    }
    __syncthreads();
}

__global__ void mps_init_kernel() {
    int i = blockIdx.x * NTHR + threadIdx.x;   // 576*256 = 147456 threads
    if (i == 0) g_barcnt = 0u;
    if (i < 131072) {
        g_L[0][i] = (i == 0) ? 1.0f : 0.0f;
    } else {
        int j = i - 131072;
        g_N[0][j] = (j == 0) ? 1.0f : 0.0f;
    }
}

// Phase A: 32-row x 64-col tile, K=128, f32x2 packed.
__device__ __forceinline__ void tileA_compute(const float* A, const float* B,
                                              int lane, int wid, ull acc[4]) {
    acc[0] = acc[1] = acc[2] = acc[3] = 0ull;
#pragma unroll 4
    for (int k = 0; k < 128; ++k) {
        float av = A[k * 32 + lane];
        ull av2; PACK2(av2, av);
        ulonglong2 b0 = *(const ulonglong2*)(B + k * 64 + wid * 8);
        ulonglong2 b1 = *(const ulonglong2*)(B + k * 64 + wid * 8 + 4);
        FFMA2(acc[0], av2, b0.x);
        FFMA2(acc[1], av2, b0.y);
        FFMA2(acc[2], av2, b1.x);
        FFMA2(acc[3], av2, b1.y);
    }
}

__global__ void __launch_bounds__(NTHR, 1)
mps_kernel(const float* __restrict__ Mg, const float* __restrict__ Hg, float* __restrict__ out) {
    extern __shared__ __align__(16) char smem[];
    const int bid = blockIdx.x;
    const int tid = threadIdx.x;
    const int lane = tid & 31, wid = tid >> 5;
    unsigned nb = 0;
    int cur = 0;

    float* smA  = (float*)(smem + OFF_A);
    float* smB  = (float*)(smem + OFF_B);
    float* smM  = (float*)(smem + OFF_M);
    float* smH  = (float*)(smem + OFF_H);
    float* smT1 = (float*)(smem + OFF_T1S);
    ull*   smT2p = (ull*)(smem + OFF_T2P);
    float* smMn = (float*)(smem + OFF_MN);
    float* smTn = (float*)(smem + OFF_TNS);
    float* smPartF = (float*)(smem + OFF_PART);
    ull*   smPartU = (ull*)(smem + OFF_PART);

    const bool isE = (bid < 128);
    const int w_   = isE ? (bid >> 4) : 0;
    const int bch  = isE ? ((bid >> 2) & 3) : ((bid - 128) >> 2);
    const int ipch = isE ? (bid & 3) : ((bid - 128) & 3);
    const int p0g  = isE ? 0 : (((bid - 128) >> 2) * 32);
    const int q0g  = isE ? 0 : (((bid - 128) & 3) * 32);

    for (int s = 0; s < NSITE; ++s) {
        const float* m = Mg + s * 32768;   // m[a][i][p] = a*256+i*128+p; as [k=(2b+j)][q] = k*128+q
        const float* h = Hg + s * 256;
        const int nxt = cur ^ 1;

        // ============ prefetch (group 0: A,B,h | group 1: m) ============
        {
            const float* Abase = isE ? (g_L[cur] + w_ * 128 + bch * 32)
                                     : (g_N[cur] + bch * 32);
            const int kstr = isE ? 1024 : 128;
            const float* Bbase = m + ipch * 64;
            for (int t = tid; t < 1024; t += NTHR)
                cp16(smA + (t >> 3) * 32 + (t & 7) * 4, Abase + (t >> 3) * kstr + (t & 7) * 4);
            for (int t = tid; t < 2048; t += NTHR)
                cp16(smB + (t >> 4) * 64 + (t & 15) * 4, Bbase + (t >> 4) * 256 + (t & 15) * 4);
            if (isE) {
                for (int t = tid; t < 64; t += NTHR)
                    cp16(smH + t * 4, h + t * 4);
            }
            cp_commit();
            if (isE) {
                for (int t = tid; t < 8192; t += NTHR)
                    cp16(smM + t * 4, m + t * 4);
            } else {
                for (int t = tid; t < 2048; t += NTHR)
                    cp16(smMn + (t >> 3) * 32 + (t & 7) * 4, m + (t >> 3) * 128 + q0g + (t & 7) * 4);
            }
            cp_commit();
        }
        cp_wait<1>();
        __syncthreads();

        // ============ Phase A ============
        {
            ull acc[4];
            tileA_compute(smA, smB, lane, wid, acc);
            int b = bch * 32 + lane;
            if (isE) {
#pragma unroll
                for (int u = 0; u < 4; ++u) {
                    float2 f = unpk(acc[u]);
                    int col = ipch * 64 + wid * 8 + 2 * u;     // col = i*128 + p
                    int i = col >> 7, p = col & 127;
                    g_T1[p * 2048 + (w_ * 2 + i) * 128 + b] = f.x;
                    g_T1[(p + 1) * 2048 + (w_ * 2 + i) * 128 + b] = f.y;
                }
            } else {
#pragma unroll
                for (int u = 0; u < 4; ++u) {
                    float2 f = unpk(acc[u]);
                    int col = ipch * 64 + wid * 8 + 2 * u;
                    int i = col >> 7, p = col & 127;
                    *(float2*)&g_Tn[(b * 2 + i) * 128 + p] = f;   // transposed, p even
                }
            }
        }
        ++nb; gridbar(nb * NCTA);

        // ============ Phase B ============
        if (isE) {
            const int p = bid;
            for (int t = tid; t < 512; t += NTHR)
                cp16(smT1 + t * 4, g_T1 + p * 2048 + t * 4);
            cp_commit();
            cp_wait<0>();
            __syncthreads();
            // T2p[k][x] = packed pair (v,v), v = sum_{w,i} T1[(w,i)][b] h[w,x,i,j], k=2b+j=tid
            {
                const int b = tid >> 1, j = tid & 1;
                float t1v[16];
#pragma unroll
                for (int wi = 0; wi < 16; ++wi) t1v[wi] = smT1[wi * 128 + b];
#pragma unroll
                for (int x = 0; x < 8; ++x) {
                    float a = 0.0f;
#pragma unroll
                    for (int wi = 0; wi < 16; ++wi)
                        a += t1v[wi] * smH[(wi >> 1) * 32 + x * 4 + (wi & 1) * 2 + j];
                    ull pk; PACK2(pk, a);
                    smT2p[tid * 8 + x] = pk;
                }
            }
            __syncthreads();
            // main: warp w handles k in [w*32, w*32+32); thread: all 8 x, q = lane*4..+3
            ull acc[8][2];
#pragma unroll
            for (int x = 0; x < 8; ++x) { acc[x][0] = 0ull; acc[x][1] = 0ull; }
#pragma unroll 2
            for (int kk = 0; kk < 32; ++kk) {
                const int k = wid * 32 + kk;
                ulonglong2 mv = *(const ulonglong2*)(smM + k * 128 + lane * 4);
                ulonglong2 ta = *(const ulonglong2*)(smT2p + k * 8);
                ulonglong2 tb = *(const ulonglong2*)(smT2p + k * 8 + 2);
                ulonglong2 tc = *(const ulonglong2*)(smT2p + k * 8 + 4);
                ulonglong2 td = *(const ulonglong2*)(smT2p + k * 8 + 6);
                FFMA2(acc[0][0], ta.x, mv.x); FFMA2(acc[0][1], ta.x, mv.y);
                FFMA2(acc[1][0], ta.y, mv.x); FFMA2(acc[1][1], ta.y, mv.y);
                FFMA2(acc[2][0], tb.x, mv.x); FFMA2(acc[2][1], tb.x, mv.y);
                FFMA2(acc[3][0], tb.y, mv.x); FFMA2(acc[3][1], tb.y, mv.y);
                FFMA2(acc[4][0], tc.x, mv.x); FFMA2(acc[4][1], tc.x, mv.y);
                FFMA2(acc[5][0], tc.y, mv.x); FFMA2(acc[5][1], tc.y, mv.y);
                FFMA2(acc[6][0], td.x, mv.x); FFMA2(acc[6][1], td.x, mv.y);
                FFMA2(acc[7][0], td.y, mv.x); FFMA2(acc[7][1], td.y, mv.y);
            }
            // partial[w][x][q] floats
#pragma unroll
            for (int x = 0; x < 8; ++x) {
                ulonglong2 v; v.x = acc[x][0]; v.y = acc[x][1];
                *(ulonglong2*)(smPartF + wid * 1024 + x * 128 + lane * 4) = v;
            }
            __syncthreads();
            {
                const int x = wid;
                ull r0 = 0ull, r1 = 0ull;
#pragma unroll
                for (int w2 = 0; w2 < 8; ++w2) {
                    ulonglong2 v = *(const ulonglong2*)(smPartF + w2 * 1024 + x * 128 + lane * 4);
                    FADD2(r0, v.x); FADD2(r1, v.y);
                }
                ulonglong2 o; o.x = r0; o.y = r1;
                *(ulonglong2*)&g_L[nxt][p * 1024 + x * 128 + lane * 4] = o;
            }
        } else {
            // stage Tn rows [256][p0g..p0g+32)
            for (int t = tid; t < 2048; t += NTHR)
                cp16(smTn + (t >> 3) * 32 + (t & 7) * 4,
                     g_Tn + (t >> 3) * 128 + p0g + (t & 7) * 4);
            cp_commit();
            cp_wait<0>();
            __syncthreads();
            // main: warp w -> k in [w*32,+32); thread: q = lane, all 32 p as 16 pairs
            ull acc[16];
#pragma unroll
            for (int u = 0; u < 16; ++u) acc[u] = 0ull;
#pragma unroll 2
            for (int kk = 0; kk < 32; ++kk) {
                const int k = wid * 32 + kk;
                float mq = smMn[k * 32 + lane];
                ull mq2; PACK2(mq2, mq);
#pragma unroll
                for (int c = 0; c < 8; ++c) {
                    ulonglong2 u = *(const ulonglong2*)(smTn + k * 32 + c * 4);
                    FFMA2(acc[2 * c], u.x, mq2);
                    FFMA2(acc[2 * c + 1], u.y, mq2);
                }
            }
            // partial[w][pp][q] ull pairs
#pragma unroll
            for (int pp = 0; pp < 16; ++pp)
                smPartU[wid * 512 + pp * 32 + lane] = acc[pp];
            __syncthreads();
            {
#pragma unroll
                for (int half = 0; half < 2; ++half) {
                    const int pp = wid + half * 8;
                    ull r = 0ull;
#pragma unroll
                    for (int w2 = 0; w2 < 8; ++w2)
                        FADD2(r, smPartU[w2 * 512 + pp * 32 + lane]);
                    float2 f = unpk(r);
                    g_N[nxt][(p0g + 2 * pp) * 128 + q0g + lane] = f.x;
                    g_N[nxt][(p0g + 2 * pp + 1) * 128 + q0g + lane] = f.y;
                }
            }
        }
        ++nb; gridbar(nb * NCTA);

        cur = nxt;
    }

    if (bid == 0 && tid == 0) {
        volatile float* Lv = g_L[cur];
        volatile float* Nv = g_N[cur];
        float e = Lv[7 * 128];    // L[0, W-1, 0]
        float n = Nv[0];          // N[0, 0]
        out[0] = e;
        out[1] = n;
        out[2] = e / n;
        out[3] = fmaxf(n - 10000.0f, 0.0f);
    }
}

extern "C" void kernel_launch(void* const* d_in, const int* in_sizes, int n_in,
                              void* d_out, int out_size) {
    const float* M = (const float*)d_in[0];
    const float* H = (const float*)d_in[1];
    float* out = (float*)d_out;
    cudaFuncSetAttribute(mps_kernel, cudaFuncAttributeMaxDynamicSharedMemorySize, SMEM_BYTES);
    mps_init_kernel<<<576, NTHR>>>();
    mps_kernel<<<NCTA, NTHR, SMEM_BYTES>>>(M, H, out);
}

// round 5
// speedup vs baseline: 3.0202x; 1.3709x over previous
#include <cuda_runtime.h>

#define NSITE 40
#define NSTEP 20
#define NCTA  144
#define NTHR  256

typedef unsigned long long ull;

__device__ __align__(16) float g_L[2][131072];   // left  env [a][w][b]
__device__ __align__(16) float g_R[2][131072];   // right env [a][x][b]
__device__ __align__(16) float g_N[2][16384];
__device__ __align__(16) float g_Nr[2][16384];
__device__ __align__(16) float g_T1[262144];     // left  T1 [p][(2w+i)][b]
__device__ __align__(16) float g_T1r[262144];    // right T1
__device__ __align__(16) float g_Tn[32768];      // left  Tn transposed [k][p]
__device__ __align__(16) float g_Tnr[32768];
__device__ __align__(16) float g_mT[655360];     // sites 20..39: [p*256+i*128+a] = m[a,i,p]
__device__ __align__(16) float g_hT[5120];       // sites 20..39: [x*32+w*4+i*2+j] = h[w,x,i,j]
__device__ float g_parts[NCTA];
__device__ unsigned g_barcnt;

// smem layout (bytes), energy CTA:
//   smM 0..131072 | smT2p 131072..163840 ([2pl][8x][256k] ull)
//   smA 163840(16K) | smH 180224(1K) | smT1 181248(16K)
//   smPartE @163840 (32K, aliases A/H/T1 after they are dead)
// norm CTA: smM 0.. | smTn 131072(32K) | smAn 163840(16K) | smPartN 180224(32K)
#define SMEM_BYTES 212992
#define OFF_M    0
#define OFF_T2P  131072
#define OFF_A    163840
#define OFF_H    180224
#define OFF_T1S  181248
#define OFF_PE   163840
#define OFF_TN   131072
#define OFF_AN   163840
#define OFF_PN   180224

__device__ __forceinline__ void cp16(void* s, const void* g) {
    unsigned sa = (unsigned)__cvta_generic_to_shared(s);
    asm volatile("cp.async.cg.shared.global [%0], [%1], 16;" :: "r"(sa), "l"(g));
}
__device__ __forceinline__ void cp_commit() { asm volatile("cp.async.commit_group;"); }
template <int N> __device__ __forceinline__ void cp_wait() {
    asm volatile("cp.async.wait_group %0;" :: "n"(N));
}
#define PACK2(d, s) asm("mov.b64 %0, {%1, %1};" : "=l"(d) : "r"(__float_as_uint(s)))
#define FFMA2(acc, a, b) asm("fma.rn.f32x2 %0, %1, %2, %0;" : "+l"(acc) : "l"(a), "l"(b))
#define FADD2(acc, a)    asm("add.rn.f32x2 %0, %0, %1;"     : "+l"(acc) : "l"(a))

__device__ __forceinline__ float2 unpk(ull v) {
    unsigned lo, hi;
    asm("mov.b64 {%0, %1}, %2;" : "=r"(lo), "=r"(hi) : "l"(v));
    float2 f; f.x = __uint_as_float(lo); f.y = __uint_as_float(hi);
    return f;
}

__device__ __forceinline__ void gridbar(unsigned target) {
    __syncthreads();
    if (threadIdx.x == 0) {
        asm volatile("red.release.gpu.global.add.u32 [%0], 1;" :: "l"(&g_barcnt) : "memory");
        unsigned v;
        do {
            asm volatile("ld.acquire.gpu.global.u32 %0, [%1];" : "=r"(v) : "l"(&g_barcnt) : "memory");
        } while (v < target);
    }
    __syncthreads();
}

__global__ void mps_init_kernel(const float* __restrict__ Mg, const float* __restrict__ Hg) {
    int i = blockIdx.x * NTHR + threadIdx.x;       // 3732*256 >= 955392
    if (i == 0) g_barcnt = 0u;
    if (i < 655360) {
        int s = i >> 15, r = i & 32767;
        int p = r >> 8, ii = (r >> 7) & 1, a = r & 127;
        g_mT[i] = Mg[(20 + s) * 32768 + a * 256 + ii * 128 + p];
    } else if (i < 660480) {
        int t = i - 655360;
        int s = t >> 8, r = t & 255;
        int x = r >> 5, w = (r >> 2) & 7, ij = r & 3;
        g_hT[t] = Hg[(20 + s) * 256 + w * 32 + x * 4 + ij];
    } else if (i < 791552) {
        int t = i - 660480; g_L[0][t] = (t == 0) ? 1.0f : 0.0f;
    } else if (i < 922624) {
        int t = i - 791552; g_R[0][t] = (t == 896) ? 1.0f : 0.0f;  // [0][W-1][0]
    } else if (i < 939008) {
        int t = i - 922624; g_N[0][t] = (t == 0) ? 1.0f : 0.0f;
    } else if (i < 955392) {
        int t = i - 939008; g_Nr[0][t] = (t == 0) ? 1.0f : 0.0f;
    }
}

__global__ void __launch_bounds__(NTHR, 1)
mps_kernel(const float* __restrict__ Mg, const float* __restrict__ Hg, float* __restrict__ out) {
    extern __shared__ __align__(16) char smem[];
    const int bid = blockIdx.x;
    const int tid = threadIdx.x;
    const int lane = tid & 31, wid = tid >> 5;
    unsigned nb = 0;
    int cur = 0;

    float* smM  = (float*)(smem + OFF_M);
    ull*   smT2p = (ull*)(smem + OFF_T2P);
    float* smA  = (float*)(smem + OFF_A);
    float* smH  = (float*)(smem + OFF_H);
    float* smT1 = (float*)(smem + OFF_T1S);
    float* smPE = (float*)(smem + OFF_PE);
    float* smTn = (float*)(smem + OFF_TN);
    float* smAn = (float*)(smem + OFF_AN);
    ull*   smPN = (ull*)(smem + OFF_PN);

    const bool isE = (bid < 128);
    const int dir = isE ? (bid >> 6) : ((bid - 128) >> 3);
    const int e   = bid & 63;
    const int rn  = (bid - 128) & 7;
    // phase A tile coords (energy: w(8) x bch(4) x cch(2); norm: bch(4) x cch(2))
    const int w_  = isE ? (e >> 3) : 0;
    const int bch = isE ? ((e >> 1) & 3) : (rn >> 1);
    const int cch = isE ? (e & 1) : (rn & 1);
    const int p0  = 2 * e;                 // energy phase B
    const int p0n = (rn >> 1) * 32;        // norm phase B
    const int q0n = (rn & 1) * 64;
    float* T1g = dir ? g_T1r : g_T1;
    float* Tng = dir ? g_Tnr : g_Tn;

    for (int s = 0; s < NSTEP; ++s) {
        const int site = dir ? (NSITE - 1 - s) : s;
        const float* mp = dir ? (g_mT + (site - 20) * 32768) : (Mg + site * 32768);
        const float* hp = dir ? (g_hT + (site - 20) * 256) : (Hg + site * 256);
        const float* envEc = dir ? g_R[cur] : g_L[cur];
        float*       envEn = dir ? g_R[cur ^ 1] : g_L[cur ^ 1];
        const float* envNc = dir ? g_Nr[cur] : g_N[cur];
        float*       envNn = dir ? g_Nr[cur ^ 1] : g_N[cur ^ 1];

        // ---------- prefetch: group1 = env tile (+h) + m half(cch); group2 = m other half
        if (isE) {
            const float* Ab = envEc + w_ * 128 + bch * 32;
            for (int t = tid; t < 1024; t += NTHR)
                cp16(smA + (t >> 3) * 32 + (t & 7) * 4, Ab + (t >> 3) * 1024 + (t & 7) * 4);
            if (tid < 64) cp16(smH + tid * 4, hp + tid * 4);
            for (int t = tid; t < 4096; t += NTHR)
                cp16(smM + (t >> 5) * 256 + cch * 128 + (t & 31) * 4,
                     mp + (t >> 5) * 256 + cch * 128 + (t & 31) * 4);
            cp_commit();
            for (int t = tid; t < 4096; t += NTHR)
                cp16(smM + (t >> 5) * 256 + (cch ^ 1) * 128 + (t & 31) * 4,
                     mp + (t >> 5) * 256 + (cch ^ 1) * 128 + (t & 31) * 4);
            cp_commit();
        } else {
            const float* Ab = envNc + bch * 32;
            for (int t = tid; t < 1024; t += NTHR)
                cp16(smAn + (t >> 3) * 32 + (t & 7) * 4, Ab + (t >> 3) * 128 + (t & 7) * 4);
            for (int t = tid; t < 4096; t += NTHR)
                cp16(smM + (t >> 5) * 256 + cch * 128 + (t & 31) * 4,
                     mp + (t >> 5) * 256 + cch * 128 + (t & 31) * 4);
            cp_commit();
            for (int t = tid; t < 4096; t += NTHR)
                cp16(smM + (t >> 5) * 256 + (cch ^ 1) * 128 + (t & 31) * 4,
                     mp + (t >> 5) * 256 + (cch ^ 1) * 128 + (t & 31) * 4);
            cp_commit();
        }
        cp_wait<1>();
        __syncthreads();

        // ---------- Phase A: 32 rows x 128 cols, K=128 ----------
        {
            const float* Ab = isE ? smA : smAn;
            ull acc[8];
#pragma unroll
            for (int u = 0; u < 8; ++u) acc[u] = 0ull;
#pragma unroll 4
            for (int k = 0; k < 128; ++k) {
                float av = Ab[k * 32 + lane];
                ull av2; PACK2(av2, av);
                const ulonglong2* bp = (const ulonglong2*)(smM + k * 256 + cch * 128 + wid * 16);
                ulonglong2 b0 = bp[0], b1 = bp[1], b2 = bp[2], b3 = bp[3];
                FFMA2(acc[0], av2, b0.x); FFMA2(acc[1], av2, b0.y);
                FFMA2(acc[2], av2, b1.x); FFMA2(acc[3], av2, b1.y);
                FFMA2(acc[4], av2, b2.x); FFMA2(acc[5], av2, b2.y);
                FFMA2(acc[6], av2, b3.x); FFMA2(acc[7], av2, b3.y);
            }
            const int b = bch * 32 + lane;
            if (isE) {
#pragma unroll
                for (int u = 0; u < 8; ++u) {
                    float2 f = unpk(acc[u]);
                    int col = cch * 128 + wid * 16 + 2 * u;     // col = i*128 + p
                    int i = col >> 7, p = col & 127;
                    T1g[p * 2048 + (w_ * 2 + i) * 128 + b] = f.x;
                    T1g[(p + 1) * 2048 + (w_ * 2 + i) * 128 + b] = f.y;
                }
            } else {
#pragma unroll
                for (int u = 0; u < 8; ++u) {
                    float2 f = unpk(acc[u]);
                    int col = cch * 128 + wid * 16 + 2 * u;
                    int i = col >> 7, p = col & 127;
                    *(float2*)&Tng[(b * 2 + i) * 128 + p] = f;
                }
            }
        }
        ++nb; gridbar(nb * NCTA);

        // ---------- Phase B ----------
        if (isE) {
            for (int t = tid; t < 1024; t += NTHR)        // T1 rows p0, p0+1 (contiguous)
                cp16(smT1 + t * 4, T1g + p0 * 2048 + t * 4);
            cp_commit();
            cp_wait<0>();
            __syncthreads();
            // T2p[pl][x][k=2b+j] packed
            {
                const int b = tid >> 1, j = tid & 1;
#pragma unroll
                for (int pl = 0; pl < 2; ++pl) {
                    float t1v[16];
#pragma unroll
                    for (int wi = 0; wi < 16; ++wi) t1v[wi] = smT1[pl * 2048 + wi * 128 + b];
#pragma unroll
                    for (int x = 0; x < 8; ++x) {
                        float a = 0.0f;
#pragma unroll
                        for (int wi = 0; wi < 16; ++wi)
                            a += t1v[wi] * smH[(wi >> 1) * 32 + x * 4 + (wi & 1) * 2 + j];
                        ull pk; PACK2(pk, a);
                        smT2p[(pl * 8 + x) * 256 + tid] = pk;
                    }
                }
            }
            __syncthreads();
            // main: warp = (pl = wid>>2, kq = wid&3); thread: 8 x * 4 q
            {
                const int pl = wid >> 2, kq = wid & 3;
                ull acc[16];
#pragma unroll
                for (int u = 0; u < 16; ++u) acc[u] = 0ull;
#pragma unroll 2
                for (int kk = 0; kk < 64; ++kk) {
                    const int k = kq * 64 + kk;
                    ulonglong2 mv = *(const ulonglong2*)(smM + k * 128 + lane * 4);
#pragma unroll
                    for (int x = 0; x < 8; ++x) {
                        ull tx = smT2p[(pl * 8 + x) * 256 + k];
                        FFMA2(acc[2 * x], tx, mv.x);
                        FFMA2(acc[2 * x + 1], tx, mv.y);
                    }
                }
#pragma unroll
                for (int x = 0; x < 8; ++x) {
                    ulonglong2 v; v.x = acc[2 * x]; v.y = acc[2 * x + 1];
                    *(ulonglong2*)(smPE + ((pl * 4 + kq) * 8 + x) * 128 + lane * 4) = v;
                }
            }
            __syncthreads();
            {
                const int pl = tid >> 7, x = (tid >> 4) & 7, qg = (tid & 15) * 8;
                ull r[4] = {0ull, 0ull, 0ull, 0ull};
#pragma unroll
                for (int kq = 0; kq < 4; ++kq) {
                    const float* bp = smPE + ((pl * 4 + kq) * 8 + x) * 128 + qg;
                    ulonglong2 v0 = *(const ulonglong2*)bp;
                    ulonglong2 v1 = *(const ulonglong2*)(bp + 4);
                    FADD2(r[0], v0.x); FADD2(r[1], v0.y);
                    FADD2(r[2], v1.x); FADD2(r[3], v1.y);
                }
                float* o = envEn + (p0 + pl) * 1024 + x * 128 + qg;
                ulonglong2 w0; w0.x = r[0]; w0.y = r[1];
                ulonglong2 w1; w1.x = r[2]; w1.y = r[3];
                *(ulonglong2*)o = w0; *(ulonglong2*)(o + 4) = w1;
            }
        } else {
            for (int t = tid; t < 2048; t += NTHR)        // Tn [256][32 p-slice]
                cp16(smTn + (t >> 3) * 32 + (t & 7) * 4,
                     Tng + (t >> 3) * 128 + p0n + (t & 7) * 4);
            cp_commit();
            cp_wait<0>();
            __syncthreads();
            {
                const int qh = wid & 1, kq = wid >> 1;
                const int q = q0n + qh * 32 + lane;
                ull acc[16];
#pragma unroll
                for (int u = 0; u < 16; ++u) acc[u] = 0ull;
#pragma unroll 2
                for (int kk = 0; kk < 64; ++kk) {
                    const int k = kq * 64 + kk;
                    float mq = smM[k * 128 + q];
                    ull mq2; PACK2(mq2, mq);
#pragma unroll
                    for (int c = 0; c < 8; ++c) {
                        ulonglong2 u2 = *(const ulonglong2*)(smTn + k * 32 + c * 4);
                        FFMA2(acc[2 * c], u2.x, mq2);
                        FFMA2(acc[2 * c + 1], u2.y, mq2);
                    }
                }
#pragma unroll
                for (int u = 0; u < 16; ++u)
                    smPN[((kq * 2 + qh) * 16 + u) * 32 + lane] = acc[u];
            }
            __syncthreads();
            {
                const int pp = tid >> 4, qg = (tid & 15) * 4;
                const int qh = qg >> 5, ql = qg & 31;
                ull r[4] = {0ull, 0ull, 0ull, 0ull};
#pragma unroll
                for (int kq = 0; kq < 4; ++kq) {
                    const ull* bp = smPN + ((kq * 2 + qh) * 16 + pp) * 32 + ql;
                    ulonglong2 v0 = *(const ulonglong2*)bp;
                    ulonglong2 v1 = *(const ulonglong2*)(bp + 2);
                    FADD2(r[0], v0.x); FADD2(r[1], v0.y);
                    FADD2(r[2], v1.x); FADD2(r[3], v1.y);
                }
#pragma unroll
                for (int v = 0; v < 4; ++v) {
                    float2 f = unpk(r[v]);
                    int q = q0n + qg + v;
                    envNn[(p0n + 2 * pp) * 128 + q] = f.x;
                    envNn[(p0n + 2 * pp + 1) * 128 + q] = f.y;
                }
            }
        }
        ++nb; gridbar(nb * NCTA);
        cur ^= 1;
    }

    // ---------- final contraction: dot(L20,R20), dot(Nl20,Nr20) ----------
    {
        const float *Xp, *Yp; int base;
        if (isE) { Xp = g_L[cur]; Yp = g_R[cur]; base = bid * 1024; }
        else     { Xp = g_N[cur]; Yp = g_Nr[cur]; base = (bid - 128) * 1024; }
        ull dacc = 0ull;
        int t = base + tid * 4;
        ulonglong2 xa = *(const ulonglong2*)(Xp + t);
        ulonglong2 ya = *(const ulonglong2*)(Yp + t);
        FFMA2(dacc, xa.x, ya.x);
        FFMA2(dacc, xa.y, ya.y);
        float2 df = unpk(dacc);
        float v = df.x + df.y;
#pragma unroll
        for (int off = 16; off > 0; off >>= 1) v += __shfl_xor_sync(~0u, v, off);
        float* smRed = (float*)(smem + OFF_H);  // any free region
        if (lane == 0) smRed[wid] = v;
        __syncthreads();
        if (tid == 0) {
            float tot = 0.0f;
#pragma unroll
            for (int w2 = 0; w2 < 8; ++w2) tot += smRed[w2];
            g_parts[bid] = tot;
        }
    }
    ++nb; gridbar(nb * NCTA);
    if (bid == 0 && wid == 0) {
        float ev = 0.0f;
#pragma unroll
        for (int r = 0; r < 4; ++r) ev += g_parts[lane + r * 32];
        float nv = (lane < 16) ? g_parts[128 + lane] : 0.0f;
#pragma unroll
        for (int off = 16; off > 0; off >>= 1) {
            ev += __shfl_xor_sync(~0u, ev, off);
            nv += __shfl_xor_sync(~0u, nv, off);
        }
        if (lane == 0) {
            out[0] = ev;
            out[1] = nv;
            out[2] = ev / nv;
            out[3] = fmaxf(nv - 10000.0f, 0.0f);
        }
    }
}

extern "C" void kernel_launch(void* const* d_in, const int* in_sizes, int n_in,
                              void* d_out, int out_size) {
    const float* M = (const float*)d_in[0];
    const float* H = (const float*)d_in[1];
    float* out = (float*)d_out;
    cudaFuncSetAttribute(mps_kernel, cudaFuncAttributeMaxDynamicSharedMemorySize, SMEM_BYTES);
    mps_init_kernel<<<3732, NTHR>>>(M, H);
    mps_kernel<<<NCTA, NTHR, SMEM_BYTES>>>(M, H, out);
}